// round 1
// baseline (speedup 1.0000x reference)
#include <cuda_runtime.h>

// Fused 1-level DWT (analysis lowpass, stride 2, symmetric pad) + synthesis
// lowpass (transposed conv, dilation 2). 64 independent rows of length 524288.
//
// Derivation (XLA conv = cross-correlation):
//   cA[m]    = sum_i H[i] * sig_mir(2m + i - 8)
//   ya[2u]   = sum_r H[8-2r] * cA[u+r]   (r = 0..4)
//   ya[2u+1] = sum_r H[9-2r] * cA[u+r]
// mirror: q<0 -> -1-q ; q>=L -> 2L-1-q (one reflection is enough, halo <= 9).

#define TILE      2048
#define THREADS   256
#define PER_THR   8          // outputs per thread (TILE = THREADS*PER_THR)
#define SMEM_N    (TILE + 16)  // sig window [S-8, S+TILE+8)

__global__ __launch_bounds__(THREADS)
void wavelet_fused_kernel(const float* __restrict__ x,
                          float* __restrict__ y,
                          int L, int tilesPerRow)
{
    __shared__ float sx[SMEM_N];

    const int tile = blockIdx.x;
    const int row  = blockIdx.y;
    const long long rowbase = (long long)row * (long long)L;
    const int S = tile * TILE;
    const float* xr = x + rowbase;

    // ---- load sig tile [S-8, S+TILE+8) into shared memory ----
    if (tile == 0 || tile == tilesPerRow - 1) {
        // boundary tiles: scalar loads with symmetric mirroring
        for (int i = threadIdx.x; i < SMEM_N; i += THREADS) {
            int q = S - 8 + i;
            if (q < 0)        q = -1 - q;
            else if (q >= L)  q = 2 * L - 1 - q;
            sx[i] = xr[q];
        }
    } else {
        // interior tiles: vectorized (S-8 is a multiple of 8 -> 16B aligned)
        const float4* g4 = reinterpret_cast<const float4*>(xr + (S - 8));
        float4* s4 = reinterpret_cast<float4*>(sx);
        #pragma unroll
        for (int i = threadIdx.x; i < SMEM_N / 4; i += THREADS) {
            s4[i] = g4[i];
        }
    }
    __syncthreads();

    // filter taps (REC_LO); all FMAs become FFMA-imm (rt=1 on sm_103a)
    constexpr float H[10] = {
        0.160102397974125f,     0.6038292697974729f,
        0.7243085284385744f,    0.13842814590110342f,
       -0.24229488706619015f,  -0.03224486958502952f,
        0.07757149384006515f,  -0.006241490213011705f,
       -0.012580751999015526f,  0.003335725285001549f
    };

    // ---- each thread: 8 consecutive outputs t0..t0+7 (t0 even) ----
    // needs sig(t0-8 .. t0+15) = sx[tid*8 .. tid*8+23]
    float xv[24];
    const float4* sp = reinterpret_cast<const float4*>(sx + threadIdx.x * PER_THR);
    #pragma unroll
    for (int v = 0; v < 6; v++) {
        float4 t = sp[v];
        xv[4*v+0] = t.x; xv[4*v+1] = t.y; xv[4*v+2] = t.z; xv[4*v+3] = t.w;
    }

    // stage 1: 8 approximation coefficients cA[t0/2 + r], r = 0..7
    float cA[8];
    #pragma unroll
    for (int r = 0; r < 8; r++) {
        float a = 0.0f;
        #pragma unroll
        for (int i = 0; i < 10; i++) {
            a = fmaf(H[i], xv[2*r + i], a);
        }
        cA[r] = a;
    }

    // stage 2: reconstruct 8 outputs (4 even/odd pairs)
    float o[8];
    #pragma unroll
    for (int s = 0; s < 4; s++) {
        float e = 0.0f, od = 0.0f;
        #pragma unroll
        for (int rp = 0; rp < 5; rp++) {
            e  = fmaf(H[8 - 2*rp], cA[s + rp], e);
            od = fmaf(H[9 - 2*rp], cA[s + rp], od);
        }
        o[2*s + 0] = e;
        o[2*s + 1] = od;
    }

    float4* yo = reinterpret_cast<float4*>(y + rowbase + S + threadIdx.x * PER_THR);
    yo[0] = make_float4(o[0], o[1], o[2], o[3]);
    yo[1] = make_float4(o[4], o[5], o[6], o[7]);
}

extern "C" void kernel_launch(void* const* d_in, const int* in_sizes, int n_in,
                              void* d_out, int out_size)
{
    const float* x = (const float*)d_in[0];
    float* y = (float*)d_out;

    const int B = 64;
    const int total = in_sizes[0];          // 64 * 128 * 4096
    const int L = total / B;                // 524288 (row length = C*Lc)
    const int tilesPerRow = L / TILE;       // 256

    dim3 grid(tilesPerRow, B);
    wavelet_fused_kernel<<<grid, THREADS>>>(x, y, L, tilesPerRow);
}

// round 2
// speedup vs baseline: 1.3094x; 1.3094x over previous
#include <cuda_runtime.h>

// Fused 1-level DWT (analysis lowpass, stride 2, symmetric pad) + synthesis
// lowpass (transposed conv, dilation 2). 64 independent rows of length 524288.
//
//   cA[m]    = sum_i H[i] * sig_mir(2m + i - 8)
//   ya[2u]   = sum_r H[8-2r] * cA[u+r]   (r = 0..4)
//   ya[2u+1] = sum_r H[9-2r] * cA[u+r]
// mirror: q<0 -> -1-q ; q>=L -> 2L-1-q (one reflection suffices, halo <= 9).
//
// R2: no shared memory. Each thread loads its 24-float input window directly
// from global as 6 overlapping LDG.128; L1 dedupes the overlap (same 128B
// lines across lanes). Cuts L1 traffic 24 -> 16 B/elem and removes STS+BAR.

#define TILE      2048
#define THREADS   256
#define PER_THR   8          // outputs per thread (TILE = THREADS*PER_THR)

__device__ __forceinline__ void wavelet_compute(const float xv[24], float o[8])
{
    constexpr float H[10] = {
        0.160102397974125f,     0.6038292697974729f,
        0.7243085284385744f,    0.13842814590110342f,
       -0.24229488706619015f,  -0.03224486958502952f,
        0.07757149384006515f,  -0.006241490213011705f,
       -0.012580751999015526f,  0.003335725285001549f
    };

    // stage 1: 8 approximation coefficients
    float cA[8];
    #pragma unroll
    for (int r = 0; r < 8; r++) {
        float a = 0.0f;
        #pragma unroll
        for (int i = 0; i < 10; i++) {
            a = fmaf(H[i], xv[2*r + i], a);
        }
        cA[r] = a;
    }

    // stage 2: 8 outputs (4 even/odd pairs)
    #pragma unroll
    for (int s = 0; s < 4; s++) {
        float e = 0.0f, od = 0.0f;
        #pragma unroll
        for (int rp = 0; rp < 5; rp++) {
            e  = fmaf(H[8 - 2*rp], cA[s + rp], e);
            od = fmaf(H[9 - 2*rp], cA[s + rp], od);
        }
        o[2*s + 0] = e;
        o[2*s + 1] = od;
    }
}

__global__ __launch_bounds__(THREADS)
void wavelet_fused_kernel(const float* __restrict__ x,
                          float* __restrict__ y,
                          int L, int tilesPerRow)
{
    const int tile = blockIdx.x;
    const int row  = blockIdx.y;
    const long long rowbase = (long long)row * (long long)L;
    const float* xr = x + rowbase;

    const int t0 = tile * TILE + threadIdx.x * PER_THR;   // first output index

    float xv[24];

    if (tile == 0 || tile == tilesPerRow - 1) {
        // boundary: scalar mirrored loads (128 of 16384 blocks)
        #pragma unroll
        for (int i = 0; i < 24; i++) {
            int q = t0 - 8 + i;
            if (q < 0)        q = -1 - q;
            else if (q >= L)  q = 2 * L - 1 - q;
            xv[i] = xr[q];
        }
    } else {
        // interior: 6 overlapping LDG.128 (t0-8 is a multiple of 8 -> 16B aligned)
        const float4* g4 = reinterpret_cast<const float4*>(xr + (t0 - 8));
        #pragma unroll
        for (int v = 0; v < 6; v++) {
            float4 t = g4[v];
            xv[4*v+0] = t.x; xv[4*v+1] = t.y; xv[4*v+2] = t.z; xv[4*v+3] = t.w;
        }
    }

    float o[8];
    wavelet_compute(xv, o);

    float4* yo = reinterpret_cast<float4*>(y + rowbase + t0);
    yo[0] = make_float4(o[0], o[1], o[2], o[3]);
    yo[1] = make_float4(o[4], o[5], o[6], o[7]);
}

extern "C" void kernel_launch(void* const* d_in, const int* in_sizes, int n_in,
                              void* d_out, int out_size)
{
    const float* x = (const float*)d_in[0];
    float* y = (float*)d_out;

    const int B = 64;
    const int total = in_sizes[0];          // 64 * 128 * 4096
    const int L = total / B;                // 524288
    const int tilesPerRow = L / TILE;       // 256

    dim3 grid(tilesPerRow, B);
    wavelet_fused_kernel<<<grid, THREADS>>>(x, y, L, tilesPerRow);
}